// round 12
// baseline (speedup 1.0000x reference)
#include <cuda_runtime.h>
#include <cstdint>
#include <math.h>

// ============================================================================
// CRF token loss: B=512, T=2048, L=37.  loss = -(sum_b num_b - denom_b)/n_tok
// R11: chunked forward (contraction warm-up) with bf16x2-compressed broadcast
// shuffles: q-pair packed to one b32 -> 19 SHFL.b32 per chain-step (was 38),
// unpacked to f32x2 via shift/mask (bf16->f32 is <<16). All FMA math in f32;
// M exact f32 in registers. Renorm exponent read from bf16 broadcast bits.
// 2048 warps: one warp per (batch, chunk-pair); 2 chains share one M copy.
// ============================================================================

#define LSTATE 37
#define TLEN   2048
#define BATCH  512
#define NCH    8
#define CSTEP  256
#define WARM   16
#define PF     4
#define NGROUPS ((WARM + CSTEP) / PF)   // 68
#define WARMG   (WARM / PF)             // 4
#define FULLMASK 0xffffffffu

// g_Mcol[j][i2] = ( exp(T[2*i2][j]), exp(T[2*i2+1][j]) ); col 37 = zeros,
// i2=18 hi-component = 0 (row-37 padding).
__device__ __align__(16) float2 g_Mcol[38 * 19];
__device__ float g_num[BATCH];
__device__ int   g_msum[BATCH];
__device__ float g_chunk[BATCH * NCH];
__device__ int   g_done;

// ---- f32x2 helpers ---------------------------------------------------------
__device__ __forceinline__ void fma2(unsigned long long& acc,
                                     unsigned long long a, unsigned long long b) {
    asm("fma.rn.f32x2 %0, %1, %2, %0;" : "+l"(acc) : "l"(a), "l"(b));
}
__device__ __forceinline__ unsigned long long add2(unsigned long long a,
                                                   unsigned long long b) {
    unsigned long long c;
    asm("add.rn.f32x2 %0, %1, %2;" : "=l"(c) : "l"(a), "l"(b));
    return c;
}
__device__ __forceinline__ float lo32(unsigned long long v) {
    return __uint_as_float((unsigned)v);
}
__device__ __forceinline__ float hi32(unsigned long long v) {
    return __uint_as_float((unsigned)(v >> 32));
}
__device__ __forceinline__ unsigned long long pack2(float lo, float hi) {
    return (unsigned long long)__float_as_uint(lo)
         | ((unsigned long long)__float_as_uint(hi) << 32);
}
// pack (e, o) -> bf16x2 (lo = e, hi = o)
__device__ __forceinline__ unsigned packbf(float e, float o) {
    unsigned r;
    asm("cvt.rn.bf16x2.f32 %0, %1, %2;" : "=r"(r) : "f"(o), "f"(e));
    return r;
}
// bf16x2 -> f32x2 (lo = v<<16, hi = v & 0xffff0000)
__device__ __forceinline__ unsigned long long bf2f2(unsigned v) {
    unsigned lo = v << 16;
    unsigned hi = v & 0xffff0000u;
    unsigned long long r;
    asm("mov.b64 %0, {%1, %2};" : "=l"(r) : "r"(lo), "r"(hi));
    return r;
}

// ---------------------------------------------------------------------------
// Kernel 1: numerator, one block per batch; block 0 also preps M columns
// ---------------------------------------------------------------------------
__global__ void num_kernel(const float* __restrict__ em,
                           const float* __restrict__ trans,
                           const float* __restrict__ startt,
                           const float* __restrict__ endt,
                           const int*   __restrict__ labels,
                           const int*   __restrict__ mask) {
    int b = blockIdx.x, tid = threadIdx.x;
    if (b == 0) {
        for (int x = tid; x < 38 * 19; x += 256) {
            int j = x / 19, i2 = x % 19;
            float lo = 0.0f, hi = 0.0f;
            if (j < LSTATE) {
                lo = expf(trans[(2 * i2) * LSTATE + j]);
                if (2 * i2 + 1 < LSTATE)
                    hi = expf(trans[(2 * i2 + 1) * LSTATE + j]);
            }
            g_Mcol[x] = make_float2(lo, hi);
        }
        if (tid == 0) g_done = 0;
    }

    __shared__ float sacc[8];
    __shared__ int   snt[8];
    const int*   lb = labels + (size_t)b * TLEN;
    const int*   mk = mask   + (size_t)b * TLEN;
    const float* eb = em     + (size_t)b * TLEN * LSTATE;

    float acc = 0.0f; int msum = 0;
    for (int t = tid; t < TLEN; t += 256) {
        int lt = lb[t]; int m = mk[t]; msum += m;
        if (t == 0) acc += startt[lt] + eb[lt];
        else if (m) acc += trans[lb[t - 1] * LSTATE + lt]
                         + eb[(size_t)t * LSTATE + lt];
    }
    int lane = tid & 31, wid = tid >> 5;
    #pragma unroll
    for (int o = 16; o; o >>= 1) {
        acc  += __shfl_xor_sync(FULLMASK, acc,  o);
        msum += __shfl_xor_sync(FULLMASK, msum, o);
    }
    if (lane == 0) { sacc[wid] = acc; snt[wid] = msum; }
    __syncthreads();
    if (tid == 0) {
        float a = 0.0f; int n = 0;
        #pragma unroll
        for (int k = 0; k < 8; k++) { a += sacc[k]; n += snt[k]; }
        g_num[b]  = a + endt[lb[n - 1]];
        g_msum[b] = n;
    }
}

// ---------------------------------------------------------------------------
// Kernel 2: chunked forward, bf16x2-broadcast matvec, no smem in the loop.
// One warp per chunk pair; 4 warps/block; grid 512.
// ---------------------------------------------------------------------------
__global__ void __launch_bounds__(128, 4)
fwd_kernel(const float* __restrict__ em,
           const float* __restrict__ startt,
           const float* __restrict__ endt,
           const int*   __restrict__ mask,
           float* __restrict__ out) {
    __shared__ float fr[4];
    __shared__ int   fn[4];
    __shared__ int   isLast;

    int tid  = threadIdx.x;
    int lane = tid & 31;
    int w    = tid >> 5;
    int wt   = blockIdx.x * 4 + w;      // 0..2047
    int b    = wt >> 2;
    int cA   = (wt & 3) * 2;
    int cB   = cA + 1;

    const float* eb = em   + (size_t)b * TLEN * LSTATE;
    const int*   mk = mask + (size_t)b * TLEN;

    bool act   = (lane < 19);
    int  kc    = act ? lane : 18;
    int  col0  = 2 * kc;
    bool hasHi = (col0 + 1 < LSTATE);        // false only for lane 18
    int  col1  = hasHi ? (col0 + 1) : col0;

    // M: even and odd column of this lane, as i-pairs (odd col 37 -> zeros)
    unsigned long long ME[19], MO[19];
    {
        const unsigned long long* ce =
            (const unsigned long long*)g_Mcol + col0 * 19;
        int oc = hasHi ? (col0 + 1) : 37;
        const unsigned long long* co =
            (const unsigned long long*)g_Mcol + oc * 19;
        #pragma unroll
        for (int k = 0; k < 19; k++) { ME[k] = ce[k]; MO[k] = co[k]; }
    }

    // chain states as f32 scalars (quantized to bf16x2 only for broadcast)
    float aE, aO, bE, bO;
    if (cA == 0) {
        aE = expf(startt[col0] + eb[col0]);
        aO = hasHi ? expf(startt[col1] + eb[col1]) : 0.0f;
    } else {
        aE = 1.0f; aO = hasHi ? 1.0f : 0.0f;
    }
    bE = 1.0f; bO = hasHi ? 1.0f : 0.0f;

    int t0a = cA * CSTEP - (WARM - 1);
    const float* ebc0 = eb + col0;
    const float* ebc1 = eb + col1;

    // PF-slot prefetch: exp(emission pair) packed f32x2; masks as bitfields
    unsigned long long eeA[PF], eeB[PF];
    unsigned mA = 0, mB = 0;
    if (act) {
        #pragma unroll
        for (int d = 0; d < PF; d++) {
            int ta  = t0a + d;
            int tca = ta < 0 ? 0 : (ta >= TLEN ? TLEN - 1 : ta);
            eeA[d] = pack2(__expf(ebc0[(size_t)tca * LSTATE]),
                           hasHi ? __expf(ebc1[(size_t)tca * LSTATE]) : 0.0f);
            mA |= ((ta >= 1 && ta < TLEN) ? (mk[tca] & 1) : 0) << d;

            int tb  = ta + CSTEP;
            int tcb = tb >= TLEN ? TLEN - 1 : tb;
            eeB[d] = pack2(__expf(ebc0[(size_t)tcb * LSTATE]),
                           hasHi ? __expf(ebc1[(size_t)tcb * LSTATE]) : 0.0f);
            mB |= ((tb >= 1 && tb < TLEN) ? (mk[tcb] & 1) : 0) << d;
        }
    }

    int   kta = 0, ktb = 0;
    float subA = 0.0f, subB = 0.0f;

    for (int g = 0; g < NGROUPS; g++) {
        if (g == WARMG) {   // warm boundary: reference log-mass (no kt reset)
            float va = act ? (aE + aO) : 0.0f;
            float vb = act ? (bE + bO) : 0.0f;
            #pragma unroll
            for (int o = 16; o; o >>= 1) {
                va += __shfl_xor_sync(FULLMASK, va, o);
                vb += __shfl_xor_sync(FULLMASK, vb, o);
            }
            subA = (cA == 0) ? 0.0f
                 : (float)((double)kta * 0.6931471805599453) + logf(va);
            subB = (float)((double)ktb * 0.6931471805599453) + logf(vb);
        }
        #pragma unroll
        for (int u = 0; u < PF; u++) {
            unsigned long long eA = eeA[u], eB2 = eeB[u];
            int mcA = (mA >> u) & 1, mcB = (mB >> u) & 1;

            if (act) {   // refill slot u for t + PF (off critical path)
                int ta  = t0a + g * PF + u + PF;
                int tca = ta < 0 ? 0 : (ta >= TLEN ? TLEN - 1 : ta);
                eeA[u] = pack2(__expf(ebc0[(size_t)tca * LSTATE]),
                               hasHi ? __expf(ebc1[(size_t)tca * LSTATE]) : 0.0f);
                unsigned bA = (ta >= 1 && ta < TLEN) ? (mk[tca] & 1) : 0;
                mA = (mA & ~(1u << u)) | (bA << u);

                int tb  = ta + CSTEP;
                int tcb = tb >= TLEN ? TLEN - 1 : tb;
                eeB[u] = pack2(__expf(ebc0[(size_t)tcb * LSTATE]),
                               hasHi ? __expf(ebc1[(size_t)tcb * LSTATE]) : 0.0f);
                unsigned bB = (tb >= 1 && tb < TLEN) ? (mk[tcb] & 1) : 0;
                mB = (mB & ~(1u << u)) | (bB << u);
            }

            // ---- bf16x2-compressed broadcasts + f32 matvec, both chains ----
            unsigned pkA = packbf(aE, aO);
            unsigned pkB = packbf(bE, bO);
            unsigned long long xE0 = 0, xE1 = 0, xO0 = 0, xO1 = 0;
            unsigned long long yE0 = 0, yE1 = 0, yO0 = 0, yO1 = 0;
            unsigned q0a = 0, q0b = 0;
            #pragma unroll
            for (int r = 0; r < 19; r++) {
                unsigned va = __shfl_sync(FULLMASK, pkA, r);
                unsigned vb = __shfl_sync(FULLMASK, pkB, r);
                if (r == 0) { q0a = va; q0b = vb; }
                unsigned long long fa = bf2f2(va);
                unsigned long long fb = bf2f2(vb);
                if (r & 1) {
                    fma2(xE1, fa, ME[r]); fma2(xO1, fa, MO[r]);
                    fma2(yE1, fb, ME[r]); fma2(yO1, fb, MO[r]);
                } else {
                    fma2(xE0, fa, ME[r]); fma2(xO0, fa, MO[r]);
                    fma2(yE0, fb, ME[r]); fma2(yO0, fb, MO[r]);
                }
            }
            unsigned long long sae = add2(xE0, xE1), sao = add2(xO0, xO1);
            unsigned long long sbe = add2(yE0, yE1), sbo = add2(yO0, yO1);
            float sAE = lo32(sae) + hi32(sae);
            float sAO = lo32(sao) + hi32(sao);
            float sBE = lo32(sbe) + hi32(sbe);
            float sBO = lo32(sbo) + hi32(sbo);

            float nAE = mcA ? sAE * lo32(eA)  : aE;
            float nAO = mcA ? sAO * hi32(eA)  : aO;
            float nBE = mcB ? sBE * lo32(eB2) : bE;
            float nBO = mcB ? sBO * hi32(eB2) : bO;

            if (u == PF - 1) {   // exact power-of-2 renorm every PF steps
                unsigned ea_ = (q0a >> 7) & 0xffu;   // bf16 exponent of q0
                float scA = __uint_as_float((254u - ea_) << 23);
                kta += (int)ea_ - 127;
                nAE *= scA; nAO *= scA;
                unsigned eb_ = (q0b >> 7) & 0xffu;
                float scB = __uint_as_float((254u - eb_) << 23);
                ktb += (int)eb_ - 127;
                nBE *= scB; nBO *= scB;
            }
            aE = nAE; aO = nAO;
            bE = nBE; bO = nBO;
        }
    }

    // chunk contributions (ktot*ln2 + log S_end - sub); end weights for c==7
    {
        float va = act ? (aE + aO) : 0.0f;
        float vb;
        if (cB == NCH - 1)
            vb = act ? (bE * expf(endt[col0])
                        + (hasHi ? bO * expf(endt[col1]) : 0.0f)) : 0.0f;
        else
            vb = act ? (bE + bO) : 0.0f;
        #pragma unroll
        for (int o = 16; o; o >>= 1) {
            va += __shfl_xor_sync(FULLMASK, va, o);
            vb += __shfl_xor_sync(FULLMASK, vb, o);
        }
        if (lane == 0) {
            g_chunk[b * NCH + cA] =
                (float)((double)kta * 0.6931471805599453) + logf(va) - subA;
            g_chunk[b * NCH + cB] =
                (float)((double)ktb * 0.6931471805599453) + logf(vb) - subB;
        }
    }

    // ---- fused finish: last block reduces everything ----
    __threadfence();
    __syncthreads();
    if (tid == 0)
        isLast = (atomicAdd(&g_done, 1) == (int)gridDim.x - 1);
    __syncthreads();

    if (isLast) {
        __threadfence();
        float acc = 0.0f; int nt = 0;
        for (int i = tid; i < BATCH; i += 128) {
            float d = 0.0f;
            #pragma unroll
            for (int cc = 0; cc < NCH; cc++) d += g_chunk[i * NCH + cc];
            acc += g_num[i] - d;
            nt  += g_msum[i];
        }
        #pragma unroll
        for (int o = 16; o; o >>= 1) {
            acc += __shfl_xor_sync(FULLMASK, acc, o);
            nt  += __shfl_xor_sync(FULLMASK, nt,  o);
        }
        if (lane == 0) { fr[w] = acc; fn[w] = nt; }
        __syncthreads();
        if (tid == 0) {
            float tot = fr[0] + fr[1] + fr[2] + fr[3];
            int   n   = fn[0] + fn[1] + fn[2] + fn[3];
            if (n < 1) n = 1;
            out[0] = -tot / (float)n;
        }
    }
}

// ---------------------------------------------------------------------------
// Launch
// ---------------------------------------------------------------------------
extern "C" void kernel_launch(void* const* d_in, const int* in_sizes, int n_in,
                              void* d_out, int out_size) {
    const float* em     = (const float*)d_in[0];   // emissions [512,2048,37]
    const float* trans  = (const float*)d_in[1];   // transitions [37,37]
    const float* startt = (const float*)d_in[2];   // start_transitions [37]
    const float* endt   = (const float*)d_in[3];   // end_transitions [37]
    const int*   labels = (const int*)d_in[4];     // labels [512,2048]
    const int*   mask   = (const int*)d_in[5];     // attention_mask [512,2048]

    num_kernel<<<BATCH, 256>>>(em, trans, startt, endt, labels, mask);
    fwd_kernel<<<BATCH * NCH / 8, 128>>>(em, startt, endt, mask, (float*)d_out);
}

// round 13
// speedup vs baseline: 1.8372x; 1.8372x over previous
#include <cuda_runtime.h>
#include <cstdint>
#include <math.h>

// ============================================================================
// CRF token loss: B=512, T=2048, L=37.  loss = -(sum_b num_b - denom_b)/n_tok
// R12: chunked forward (contraction warm-up). Broadcast compressed to bf16x2
// AND consumed natively by bf16x2 HFMA2 (no unpack ALU, R11's mistake):
//   per chain-step: 19 SHFL.b32 + 38 fma.rn.bf16x2, M in bf16x2 regs (38).
// f32 state kept per lane; renorm exponent read from bf16 broadcast bits.
// 2048 warps: one warp per (batch, chunk-pair); 2 chains share one M copy.
// ============================================================================

#define LSTATE 37
#define TLEN   2048
#define BATCH  512
#define NCH    8
#define CSTEP  256
#define WARM   16
#define PF     4
#define NGROUPS ((WARM + CSTEP) / PF)   // 68
#define WARMG   (WARM / PF)             // 4
#define FULLMASK 0xffffffffu

// g_Mb[j*19+r] = bf16x2( exp(T[2r][j]), exp(T[2r+1][j]) ); col 37 = zeros,
// r=18 hi half = 0 (row-37 padding).
__device__ unsigned g_Mb[38 * 19];
__device__ float g_num[BATCH];
__device__ int   g_msum[BATCH];
__device__ float g_chunk[BATCH * NCH];
__device__ int   g_done;

// ---- helpers ----------------------------------------------------------------
__device__ __forceinline__ unsigned long long pack2(float lo, float hi) {
    return (unsigned long long)__float_as_uint(lo)
         | ((unsigned long long)__float_as_uint(hi) << 32);
}
__device__ __forceinline__ float lo32(unsigned long long v) {
    return __uint_as_float((unsigned)v);
}
__device__ __forceinline__ float hi32(unsigned long long v) {
    return __uint_as_float((unsigned)(v >> 32));
}
// pack (e, o) -> bf16x2 {lo=e, hi=o}
__device__ __forceinline__ unsigned packbf(float e, float o) {
    unsigned r;
    asm("cvt.rn.bf16x2.f32 %0, %1, %2;" : "=r"(r) : "f"(o), "f"(e));
    return r;
}
// bf16x2 fused multiply-add, accumulate in bf16x2
__device__ __forceinline__ void hfma2(unsigned& acc, unsigned a, unsigned b) {
    asm("fma.rn.bf16x2 %0, %1, %2, %0;" : "+r"(acc) : "r"(a), "r"(b));
}
// sum all four bf16 halves of two accumulators into f32
__device__ __forceinline__ float bfsum(unsigned a, unsigned b) {
    return __uint_as_float(a << 16) + __uint_as_float(a & 0xffff0000u)
         + __uint_as_float(b << 16) + __uint_as_float(b & 0xffff0000u);
}

// ---------------------------------------------------------------------------
// Kernel 1: numerator, one block per batch; block 0 also preps M (bf16x2)
// ---------------------------------------------------------------------------
__global__ void num_kernel(const float* __restrict__ em,
                           const float* __restrict__ trans,
                           const float* __restrict__ startt,
                           const float* __restrict__ endt,
                           const int*   __restrict__ labels,
                           const int*   __restrict__ mask) {
    int b = blockIdx.x, tid = threadIdx.x;
    if (b == 0) {
        for (int x = tid; x < 38 * 19; x += 256) {
            int j = x / 19, r = x % 19;
            float lo = 0.0f, hi = 0.0f;
            if (j < LSTATE) {
                lo = expf(trans[(2 * r) * LSTATE + j]);
                if (2 * r + 1 < LSTATE)
                    hi = expf(trans[(2 * r + 1) * LSTATE + j]);
            }
            g_Mb[x] = packbf(lo, hi);
        }
        if (tid == 0) g_done = 0;
    }

    __shared__ float sacc[8];
    __shared__ int   snt[8];
    const int*   lb = labels + (size_t)b * TLEN;
    const int*   mk = mask   + (size_t)b * TLEN;
    const float* eb = em     + (size_t)b * TLEN * LSTATE;

    float acc = 0.0f; int msum = 0;
    for (int t = tid; t < TLEN; t += 256) {
        int lt = lb[t]; int m = mk[t]; msum += m;
        if (t == 0) acc += startt[lt] + eb[lt];
        else if (m) acc += trans[lb[t - 1] * LSTATE + lt]
                         + eb[(size_t)t * LSTATE + lt];
    }
    int lane = tid & 31, wid = tid >> 5;
    #pragma unroll
    for (int o = 16; o; o >>= 1) {
        acc  += __shfl_xor_sync(FULLMASK, acc,  o);
        msum += __shfl_xor_sync(FULLMASK, msum, o);
    }
    if (lane == 0) { sacc[wid] = acc; snt[wid] = msum; }
    __syncthreads();
    if (tid == 0) {
        float a = 0.0f; int n = 0;
        #pragma unroll
        for (int k = 0; k < 8; k++) { a += sacc[k]; n += snt[k]; }
        g_num[b]  = a + endt[lb[n - 1]];
        g_msum[b] = n;
    }
}

// ---------------------------------------------------------------------------
// Kernel 2: chunked forward, bf16x2 broadcast + native bf16x2 FMA matvec.
// One warp per chunk pair; 4 warps/block; grid 512.
// ---------------------------------------------------------------------------
__global__ void __launch_bounds__(128, 4)
fwd_kernel(const float* __restrict__ em,
           const float* __restrict__ startt,
           const float* __restrict__ endt,
           const int*   __restrict__ mask,
           float* __restrict__ out) {
    __shared__ float fr[4];
    __shared__ int   fn[4];
    __shared__ int   isLast;

    int tid  = threadIdx.x;
    int lane = tid & 31;
    int w    = tid >> 5;
    int wt   = blockIdx.x * 4 + w;      // 0..2047
    int b    = wt >> 2;
    int cA   = (wt & 3) * 2;
    int cB   = cA + 1;

    const float* eb = em   + (size_t)b * TLEN * LSTATE;
    const int*   mk = mask + (size_t)b * TLEN;

    bool act   = (lane < 19);
    int  kc    = act ? lane : 18;
    int  col0  = 2 * kc;
    bool hasHi = (col0 + 1 < LSTATE);        // false only for lane 18
    int  col1  = hasHi ? (col0 + 1) : col0;

    // M columns (bf16x2 i-pairs): even col and odd col (odd col 37 -> zeros)
    unsigned MEb[19], MOb[19];
    {
        const unsigned* ce = g_Mb + col0 * 19;
        int oc = hasHi ? (col0 + 1) : 37;
        const unsigned* co = g_Mb + oc * 19;
        #pragma unroll
        for (int k = 0; k < 19; k++) { MEb[k] = ce[k]; MOb[k] = co[k]; }
    }

    // chain states as f32 (quantized to bf16x2 only for broadcast)
    float aE, aO, bE, bO;
    if (cA == 0) {
        aE = expf(startt[col0] + eb[col0]);
        aO = hasHi ? expf(startt[col1] + eb[col1]) : 0.0f;
    } else {
        aE = 1.0f; aO = hasHi ? 1.0f : 0.0f;
    }
    bE = 1.0f; bO = hasHi ? 1.0f : 0.0f;

    int t0a = cA * CSTEP - (WARM - 1);
    const float* ebc0 = eb + col0;
    const float* ebc1 = eb + col1;

    // PF-slot prefetch: exp(emission pair) packed f32x2; masks as bitfields
    unsigned long long eeA[PF], eeB[PF];
    unsigned mA = 0, mB = 0;
    #pragma unroll
    for (int d = 0; d < PF; d++) {
        int ta  = t0a + d;
        int tca = ta < 0 ? 0 : (ta >= TLEN ? TLEN - 1 : ta);
        eeA[d] = pack2(__expf(ebc0[(size_t)tca * LSTATE]),
                       hasHi ? __expf(ebc1[(size_t)tca * LSTATE]) : 0.0f);
        mA |= ((ta >= 1 && ta < TLEN) ? (mk[tca] & 1) : 0) << d;

        int tb  = ta + CSTEP;
        int tcb = tb >= TLEN ? TLEN - 1 : tb;
        eeB[d] = pack2(__expf(ebc0[(size_t)tcb * LSTATE]),
                       hasHi ? __expf(ebc1[(size_t)tcb * LSTATE]) : 0.0f);
        mB |= ((tb >= 1 && tb < TLEN) ? (mk[tcb] & 1) : 0) << d;
    }

    int   kta = 0, ktb = 0;
    float subA = 0.0f, subB = 0.0f;

    for (int g = 0; g < NGROUPS; g++) {
        if (g == WARMG) {   // warm boundary: reference log-mass (no kt reset)
            float va = act ? (aE + aO) : 0.0f;
            float vb = act ? (bE + bO) : 0.0f;
            #pragma unroll
            for (int o = 16; o; o >>= 1) {
                va += __shfl_xor_sync(FULLMASK, va, o);
                vb += __shfl_xor_sync(FULLMASK, vb, o);
            }
            subA = (cA == 0) ? 0.0f
                 : (float)((double)kta * 0.6931471805599453) + logf(va);
            subB = (float)((double)ktb * 0.6931471805599453) + logf(vb);
        }
        #pragma unroll
        for (int u = 0; u < PF; u++) {
            unsigned long long eA = eeA[u], eB2 = eeB[u];
            int mcA = (mA >> u) & 1, mcB = (mB >> u) & 1;

            {   // refill slot u for t + PF (off critical path)
                int ta  = t0a + g * PF + u + PF;
                int tca = ta < 0 ? 0 : (ta >= TLEN ? TLEN - 1 : ta);
                eeA[u] = pack2(__expf(ebc0[(size_t)tca * LSTATE]),
                               hasHi ? __expf(ebc1[(size_t)tca * LSTATE]) : 0.0f);
                unsigned bA = (ta >= 1 && ta < TLEN) ? (mk[tca] & 1) : 0;
                mA = (mA & ~(1u << u)) | (bA << u);

                int tb  = ta + CSTEP;
                int tcb = tb >= TLEN ? TLEN - 1 : tb;
                eeB[u] = pack2(__expf(ebc0[(size_t)tcb * LSTATE]),
                               hasHi ? __expf(ebc1[(size_t)tcb * LSTATE]) : 0.0f);
                unsigned bB = (tb >= 1 && tb < TLEN) ? (mk[tcb] & 1) : 0;
                mB = (mB & ~(1u << u)) | (bB << u);
            }

            // ---- bf16x2 broadcasts consumed by bf16x2 FMA, both chains ----
            unsigned pkA = packbf(aE, aO);
            unsigned pkB = packbf(bE, bO);
            unsigned xE0 = 0, xE1 = 0, xO0 = 0, xO1 = 0;   // chain A accums
            unsigned yE0 = 0, yE1 = 0, yO0 = 0, yO1 = 0;   // chain B accums
            unsigned q0a = 0, q0b = 0;
            #pragma unroll
            for (int r = 0; r < 19; r++) {
                unsigned va = __shfl_sync(FULLMASK, pkA, r);
                unsigned vb = __shfl_sync(FULLMASK, pkB, r);
                if (r == 0) { q0a = va; q0b = vb; }
                if (r & 1) {
                    hfma2(xE1, va, MEb[r]); hfma2(xO1, va, MOb[r]);
                    hfma2(yE1, vb, MEb[r]); hfma2(yO1, vb, MOb[r]);
                } else {
                    hfma2(xE0, va, MEb[r]); hfma2(xO0, va, MOb[r]);
                    hfma2(yE0, vb, MEb[r]); hfma2(yO0, vb, MOb[r]);
                }
            }
            float sAE = bfsum(xE0, xE1);
            float sAO = bfsum(xO0, xO1);
            float sBE = bfsum(yE0, yE1);
            float sBO = bfsum(yO0, yO1);

            float nAE = mcA ? sAE * lo32(eA)  : aE;
            float nAO = mcA ? sAO * hi32(eA)  : aO;
            float nBE = mcB ? sBE * lo32(eB2) : bE;
            float nBO = mcB ? sBO * hi32(eB2) : bO;

            if (u == PF - 1) {   // exact power-of-2 renorm every PF steps
                unsigned ea_ = (q0a >> 7) & 0xffu;   // bf16-lo exponent of q0
                float scA = __uint_as_float((254u - ea_) << 23);
                kta += (int)ea_ - 127;
                nAE *= scA; nAO *= scA;
                unsigned eb_ = (q0b >> 7) & 0xffu;
                float scB = __uint_as_float((254u - eb_) << 23);
                ktb += (int)eb_ - 127;
                nBE *= scB; nBO *= scB;
            }
            aE = nAE; aO = nAO;
            bE = nBE; bO = nBO;
        }
    }

    // chunk contributions (ktot*ln2 + log S_end - sub); end weights for c==7
    {
        float va = act ? (aE + aO) : 0.0f;
        float vb;
        if (cB == NCH - 1)
            vb = act ? (bE * expf(endt[col0])
                        + (hasHi ? bO * expf(endt[col1]) : 0.0f)) : 0.0f;
        else
            vb = act ? (bE + bO) : 0.0f;
        #pragma unroll
        for (int o = 16; o; o >>= 1) {
            va += __shfl_xor_sync(FULLMASK, va, o);
            vb += __shfl_xor_sync(FULLMASK, vb, o);
        }
        if (lane == 0) {
            g_chunk[b * NCH + cA] =
                (float)((double)kta * 0.6931471805599453) + logf(va) - subA;
            g_chunk[b * NCH + cB] =
                (float)((double)ktb * 0.6931471805599453) + logf(vb) - subB;
        }
    }

    // ---- fused finish: last block reduces everything ----
    __threadfence();
    __syncthreads();
    if (tid == 0)
        isLast = (atomicAdd(&g_done, 1) == (int)gridDim.x - 1);
    __syncthreads();

    if (isLast) {
        __threadfence();
        float acc = 0.0f; int nt = 0;
        for (int i = tid; i < BATCH; i += 128) {
            float d = 0.0f;
            #pragma unroll
            for (int cc = 0; cc < NCH; cc++) d += g_chunk[i * NCH + cc];
            acc += g_num[i] - d;
            nt  += g_msum[i];
        }
        #pragma unroll
        for (int o = 16; o; o >>= 1) {
            acc += __shfl_xor_sync(FULLMASK, acc, o);
            nt  += __shfl_xor_sync(FULLMASK, nt,  o);
        }
        if (lane == 0) { fr[w] = acc; fn[w] = nt; }
        __syncthreads();
        if (tid == 0) {
            float tot = fr[0] + fr[1] + fr[2] + fr[3];
            int   n   = fn[0] + fn[1] + fn[2] + fn[3];
            if (n < 1) n = 1;
            out[0] = -tot / (float)n;
        }
    }
}

// ---------------------------------------------------------------------------
// Launch
// ---------------------------------------------------------------------------
extern "C" void kernel_launch(void* const* d_in, const int* in_sizes, int n_in,
                              void* d_out, int out_size) {
    const float* em     = (const float*)d_in[0];   // emissions [512,2048,37]
    const float* trans  = (const float*)d_in[1];   // transitions [37,37]
    const float* startt = (const float*)d_in[2];   // start_transitions [37]
    const float* endt   = (const float*)d_in[3];   // end_transitions [37]
    const int*   labels = (const int*)d_in[4];     // labels [512,2048]
    const int*   mask   = (const int*)d_in[5];     // attention_mask [512,2048]

    num_kernel<<<BATCH, 256>>>(em, trans, startt, endt, labels, mask);
    fwd_kernel<<<BATCH * NCH / 8, 128>>>(em, startt, endt, mask, (float*)d_out);
}

// round 14
// speedup vs baseline: 1.9064x; 1.0377x over previous
#include <cuda_runtime.h>
#include <cstdint>
#include <math.h>

// ============================================================================
// CRF token loss: B=512, T=2048, L=37.  loss = -(sum_b num_b - denom_b)/n_tok
// R13: R12 engine (bf16x2 broadcast + native HFMA2 matvec, chunked forward
// with contraction warm-up) minus the overhead tax:
//   - mask bits via one ballot per 32 steps (no per-step mask LDG/bitfield)
//   - accumulator combine via add.rn.bf16x2 (1 HADD2 + 3 ops per sum)
//   - exact pow-2 renorm every 8 steps (group-pair unroll)
// 2048 warps: one warp per (batch, chunk-pair); 2 chains share one M copy.
// ============================================================================

#define LSTATE 37
#define TLEN   2048
#define BATCH  512
#define NCH    8
#define CSTEP  256
#define WARM   16
#define PF     4
#define NGROUPS ((WARM + CSTEP) / PF)   // 68
#define WARMG   (WARM / PF)             // 4
#define FULLMASK 0xffffffffu

// g_Mb[j*19+r] = bf16x2( exp(T[2r][j]), exp(T[2r+1][j]) ); col 37 = zeros,
// r=18 hi half = 0 (row-37 padding).
__device__ unsigned g_Mb[38 * 19];
__device__ float g_num[BATCH];
__device__ int   g_msum[BATCH];
__device__ float g_chunk[BATCH * NCH];
__device__ int   g_done;

// ---- helpers ----------------------------------------------------------------
__device__ __forceinline__ unsigned long long pack2(float lo, float hi) {
    return (unsigned long long)__float_as_uint(lo)
         | ((unsigned long long)__float_as_uint(hi) << 32);
}
__device__ __forceinline__ float lo32(unsigned long long v) {
    return __uint_as_float((unsigned)v);
}
__device__ __forceinline__ float hi32(unsigned long long v) {
    return __uint_as_float((unsigned)(v >> 32));
}
// pack (e, o) -> bf16x2 {lo=e, hi=o}
__device__ __forceinline__ unsigned packbf(float e, float o) {
    unsigned r;
    asm("cvt.rn.bf16x2.f32 %0, %1, %2;" : "=r"(r) : "f"(o), "f"(e));
    return r;
}
// bf16x2 fused multiply-add, accumulate in bf16x2
__device__ __forceinline__ void hfma2(unsigned& acc, unsigned a, unsigned b) {
    asm("fma.rn.bf16x2 %0, %1, %2, %0;" : "+r"(acc) : "r"(a), "r"(b));
}
// bf16x2 add
__device__ __forceinline__ unsigned hadd2b(unsigned a, unsigned b) {
    unsigned c;
    asm("add.rn.bf16x2 %0, %1, %2;" : "=r"(c) : "r"(a), "r"(b));
    return c;
}
// sum both bf16 halves into f32
__device__ __forceinline__ float bfsum2(unsigned z) {
    return __uint_as_float(z << 16) + __uint_as_float(z & 0xffff0000u);
}

// ---------------------------------------------------------------------------
// Kernel 1: numerator, one block per batch; block 0 also preps M (bf16x2)
// ---------------------------------------------------------------------------
__global__ void num_kernel(const float* __restrict__ em,
                           const float* __restrict__ trans,
                           const float* __restrict__ startt,
                           const float* __restrict__ endt,
                           const int*   __restrict__ labels,
                           const int*   __restrict__ mask) {
    int b = blockIdx.x, tid = threadIdx.x;
    if (b == 0) {
        for (int x = tid; x < 38 * 19; x += 256) {
            int j = x / 19, r = x % 19;
            float lo = 0.0f, hi = 0.0f;
            if (j < LSTATE) {
                lo = expf(trans[(2 * r) * LSTATE + j]);
                if (2 * r + 1 < LSTATE)
                    hi = expf(trans[(2 * r + 1) * LSTATE + j]);
            }
            g_Mb[x] = packbf(lo, hi);
        }
        if (tid == 0) g_done = 0;
    }

    __shared__ float sacc[8];
    __shared__ int   snt[8];
    const int*   lb = labels + (size_t)b * TLEN;
    const int*   mk = mask   + (size_t)b * TLEN;
    const float* eb = em     + (size_t)b * TLEN * LSTATE;

    float acc = 0.0f; int msum = 0;
    for (int t = tid; t < TLEN; t += 256) {
        int lt = lb[t]; int m = mk[t]; msum += m;
        if (t == 0) acc += startt[lt] + eb[lt];
        else if (m) acc += trans[lb[t - 1] * LSTATE + lt]
                         + eb[(size_t)t * LSTATE + lt];
    }
    int lane = tid & 31, wid = tid >> 5;
    #pragma unroll
    for (int o = 16; o; o >>= 1) {
        acc  += __shfl_xor_sync(FULLMASK, acc,  o);
        msum += __shfl_xor_sync(FULLMASK, msum, o);
    }
    if (lane == 0) { sacc[wid] = acc; snt[wid] = msum; }
    __syncthreads();
    if (tid == 0) {
        float a = 0.0f; int n = 0;
        #pragma unroll
        for (int k = 0; k < 8; k++) { a += sacc[k]; n += snt[k]; }
        g_num[b]  = a + endt[lb[n - 1]];
        g_msum[b] = n;
    }
}

// ---------------------------------------------------------------------------
// Kernel 2: chunked forward, bf16x2 broadcast + native bf16x2 FMA matvec.
// One warp per chunk pair; 4 warps/block; grid 512.
// ---------------------------------------------------------------------------
__global__ void __launch_bounds__(128, 4)
fwd_kernel(const float* __restrict__ em,
           const float* __restrict__ startt,
           const float* __restrict__ endt,
           const int*   __restrict__ mask,
           float* __restrict__ out) {
    __shared__ float fr[4];
    __shared__ int   fn[4];
    __shared__ int   isLast;

    int tid  = threadIdx.x;
    int lane = tid & 31;
    int w    = tid >> 5;
    int wt   = blockIdx.x * 4 + w;      // 0..2047
    int b    = wt >> 2;
    int cA   = (wt & 3) * 2;
    int cB   = cA + 1;

    const float* eb = em   + (size_t)b * TLEN * LSTATE;
    const int*   mk = mask + (size_t)b * TLEN;

    bool act   = (lane < 19);
    int  kc    = act ? lane : 18;
    int  col0  = 2 * kc;
    bool hasHi = (col0 + 1 < LSTATE);        // false only for lane 18
    int  col1  = hasHi ? (col0 + 1) : col0;

    // M columns (bf16x2 i-pairs): even col and odd col (odd col 37 -> zeros)
    unsigned MEb[19], MOb[19];
    {
        const unsigned* ce = g_Mb + col0 * 19;
        int oc = hasHi ? (col0 + 1) : 37;
        const unsigned* co = g_Mb + oc * 19;
        #pragma unroll
        for (int k = 0; k < 19; k++) { MEb[k] = ce[k]; MOb[k] = co[k]; }
    }

    // chain states as f32 (quantized to bf16x2 only for broadcast)
    float aE, aO, bE, bO;
    if (cA == 0) {
        aE = expf(startt[col0] + eb[col0]);
        aO = hasHi ? expf(startt[col1] + eb[col1]) : 0.0f;
    } else {
        aE = 1.0f; aO = hasHi ? 1.0f : 0.0f;
    }
    bE = 1.0f; bO = hasHi ? 1.0f : 0.0f;

    int t0a = cA * CSTEP - (WARM - 1);
    const float* ebc0 = eb + col0;
    const float* ebc1 = eb + col1;

    // PF-slot prefetch: exp(emission pair) packed f32x2
    unsigned long long eeA[PF], eeB[PF];
    #pragma unroll
    for (int d = 0; d < PF; d++) {
        int ta  = t0a + d;
        int tca = ta < 0 ? 0 : (ta >= TLEN ? TLEN - 1 : ta);
        eeA[d] = pack2(__expf(ebc0[(size_t)tca * LSTATE]),
                       hasHi ? __expf(ebc1[(size_t)tca * LSTATE]) : 0.0f);
        int tb  = ta + CSTEP;
        int tcb = tb >= TLEN ? TLEN - 1 : tb;
        eeB[d] = pack2(__expf(ebc0[(size_t)tcb * LSTATE]),
                       hasHi ? __expf(ebc1[(size_t)tcb * LSTATE]) : 0.0f);
    }

    unsigned mwA = 0, mwB = 0;    // 32-step mask words (ballot-loaded)
    int   kta = 0, ktb = 0;
    float subA = 0.0f, subB = 0.0f;

    for (int gg = 0; gg < NGROUPS / 2; gg++) {   // 34 iterations of 8 steps
        int g0 = gg * 2;
        if (g0 == WARMG) {   // warm boundary: reference log-mass (no kt reset)
            float va = act ? (aE + aO) : 0.0f;
            float vb = act ? (bE + bO) : 0.0f;
            #pragma unroll
            for (int o = 16; o; o >>= 1) {
                va += __shfl_xor_sync(FULLMASK, va, o);
                vb += __shfl_xor_sync(FULLMASK, vb, o);
            }
            subA = (cA == 0) ? 0.0f
                 : (float)((double)kta * 0.6931471805599453) + logf(va);
            subB = (float)((double)ktb * 0.6931471805599453) + logf(vb);
        }
        if ((g0 & 7) == 0) {   // reload mask words every 32 steps
            int ta = t0a + g0 * PF + lane;
            int ia = ta < 0 ? 0 : (ta >= TLEN ? TLEN - 1 : ta);
            mwA = __ballot_sync(FULLMASK,
                                (ta >= 1 && ta < TLEN) && (mk[ia] != 0));
            int tb2 = ta + CSTEP;
            int ib = tb2 >= TLEN ? TLEN - 1 : tb2;
            mwB = __ballot_sync(FULLMASK,
                                (tb2 >= 1 && tb2 < TLEN) && (mk[ib] != 0));
        }
        int shb = (g0 & 7) * PF;   // 0,8,16,24: bit base within mask word

        #pragma unroll
        for (int h = 0; h < 2; h++) {
            #pragma unroll
            for (int u = 0; u < PF; u++) {
                int g = g0 + h;
                unsigned long long eA = eeA[u], eB2 = eeB[u];
                int mcA = (mwA >> (shb + h * PF + u)) & 1;
                int mcB = (mwB >> (shb + h * PF + u)) & 1;

                {   // refill slot u for step t + PF (off critical path)
                    int ta  = t0a + g * PF + u + PF;
                    int tca = ta < 0 ? 0 : (ta >= TLEN ? TLEN - 1 : ta);
                    eeA[u] = pack2(__expf(ebc0[(size_t)tca * LSTATE]),
                                   hasHi ? __expf(ebc1[(size_t)tca * LSTATE])
                                         : 0.0f);
                    int tb  = ta + CSTEP;
                    int tcb = tb >= TLEN ? TLEN - 1 : tb;
                    eeB[u] = pack2(__expf(ebc0[(size_t)tcb * LSTATE]),
                                   hasHi ? __expf(ebc1[(size_t)tcb * LSTATE])
                                         : 0.0f);
                }

                // ---- bf16x2 broadcasts + native bf16x2 FMA, both chains ----
                unsigned pkA = packbf(aE, aO);
                unsigned pkB = packbf(bE, bO);
                unsigned xE0 = 0, xE1 = 0, xO0 = 0, xO1 = 0;   // chain A
                unsigned yE0 = 0, yE1 = 0, yO0 = 0, yO1 = 0;   // chain B
                unsigned q0a = 0, q0b = 0;
                #pragma unroll
                for (int r = 0; r < 19; r++) {
                    unsigned va = __shfl_sync(FULLMASK, pkA, r);
                    unsigned vb = __shfl_sync(FULLMASK, pkB, r);
                    if (r == 0) { q0a = va; q0b = vb; }
                    if (r & 1) {
                        hfma2(xE1, va, MEb[r]); hfma2(xO1, va, MOb[r]);
                        hfma2(yE1, vb, MEb[r]); hfma2(yO1, vb, MOb[r]);
                    } else {
                        hfma2(xE0, va, MEb[r]); hfma2(xO0, va, MOb[r]);
                        hfma2(yE0, vb, MEb[r]); hfma2(yO0, vb, MOb[r]);
                    }
                }
                float sAE = bfsum2(hadd2b(xE0, xE1));
                float sAO = bfsum2(hadd2b(xO0, xO1));
                float sBE = bfsum2(hadd2b(yE0, yE1));
                float sBO = bfsum2(hadd2b(yO0, yO1));

                float nAE = mcA ? sAE * lo32(eA)  : aE;
                float nAO = mcA ? sAO * hi32(eA)  : aO;
                float nBE = mcB ? sBE * lo32(eB2) : bE;
                float nBO = mcB ? sBO * hi32(eB2) : bO;

                if (h == 1 && u == PF - 1) {   // renorm every 8 steps
                    unsigned ea_ = (q0a >> 7) & 0xffu;   // bf16-lo exp of q0
                    float scA = __uint_as_float((254u - ea_) << 23);
                    kta += (int)ea_ - 127;
                    nAE *= scA; nAO *= scA;
                    unsigned eb_ = (q0b >> 7) & 0xffu;
                    float scB = __uint_as_float((254u - eb_) << 23);
                    ktb += (int)eb_ - 127;
                    nBE *= scB; nBO *= scB;
                }
                aE = nAE; aO = nAO;
                bE = nBE; bO = nBO;
            }
        }
    }

    // chunk contributions (ktot*ln2 + log S_end - sub); end weights for c==7
    {
        float va = act ? (aE + aO) : 0.0f;
        float vb;
        if (cB == NCH - 1)
            vb = act ? (bE * expf(endt[col0])
                        + (hasHi ? bO * expf(endt[col1]) : 0.0f)) : 0.0f;
        else
            vb = act ? (bE + bO) : 0.0f;
        #pragma unroll
        for (int o = 16; o; o >>= 1) {
            va += __shfl_xor_sync(FULLMASK, va, o);
            vb += __shfl_xor_sync(FULLMASK, vb, o);
        }
        if (lane == 0) {
            g_chunk[b * NCH + cA] =
                (float)((double)kta * 0.6931471805599453) + logf(va) - subA;
            g_chunk[b * NCH + cB] =
                (float)((double)ktb * 0.6931471805599453) + logf(vb) - subB;
        }
    }

    // ---- fused finish: last block reduces everything ----
    __threadfence();
    __syncthreads();
    if (tid == 0)
        isLast = (atomicAdd(&g_done, 1) == (int)gridDim.x - 1);
    __syncthreads();

    if (isLast) {
        __threadfence();
        float acc = 0.0f; int nt = 0;
        for (int i = tid; i < BATCH; i += 128) {
            float d = 0.0f;
            #pragma unroll
            for (int cc = 0; cc < NCH; cc++) d += g_chunk[i * NCH + cc];
            acc += g_num[i] - d;
            nt  += g_msum[i];
        }
        #pragma unroll
        for (int o = 16; o; o >>= 1) {
            acc += __shfl_xor_sync(FULLMASK, acc, o);
            nt  += __shfl_xor_sync(FULLMASK, nt,  o);
        }
        if (lane == 0) { fr[w] = acc; fn[w] = nt; }
        __syncthreads();
        if (tid == 0) {
            float tot = fr[0] + fr[1] + fr[2] + fr[3];
            int   n   = fn[0] + fn[1] + fn[2] + fn[3];
            if (n < 1) n = 1;
            out[0] = -tot / (float)n;
        }
    }
}

// ---------------------------------------------------------------------------
// Launch
// ---------------------------------------------------------------------------
extern "C" void kernel_launch(void* const* d_in, const int* in_sizes, int n_in,
                              void* d_out, int out_size) {
    const float* em     = (const float*)d_in[0];   // emissions [512,2048,37]
    const float* trans  = (const float*)d_in[1];   // transitions [37,37]
    const float* startt = (const float*)d_in[2];   // start_transitions [37]
    const float* endt   = (const float*)d_in[3];   // end_transitions [37]
    const int*   labels = (const int*)d_in[4];     // labels [512,2048]
    const int*   mask   = (const int*)d_in[5];     // attention_mask [512,2048]

    num_kernel<<<BATCH, 256>>>(em, trans, startt, endt, labels, mask);
    fwd_kernel<<<BATCH * NCH / 8, 128>>>(em, startt, endt, mask, (float*)d_out);
}

// round 16
// speedup vs baseline: 2.1332x; 1.1190x over previous
#include <cuda_runtime.h>
#include <cstdint>
#include <math.h>

// ============================================================================
// CRF token loss: B=512, T=2048, L=37.  loss = -(sum_b num_b - denom_b)/n_tok
// R15: R14 (NCH=16 chunked forward, all-bf16 state pipeline, bf16x2 broadcast
// + native HFMA2 matvec, ballot masks) with the GRID BUG fixed:
//   each block covers 8 chunks (4 warps x 2 chains) -> grid = BATCH*NCH/8
//   (R14 launched BATCH*NCH/16 = half the batches never ran -> rel_err 0.5).
// ============================================================================

#define LSTATE 37
#define TLEN   2048
#define BATCH  512
#define NCH    16
#define CSTEP  128
#define WARM   16
#define PF     4
#define NGROUPS ((WARM + CSTEP) / PF)   // 36
#define WARMG   (WARM / PF)             // 4
#define FULLMASK 0xffffffffu

// g_Mb[j*19+r] = bf16x2( exp(T[2r][j]), exp(T[2r+1][j]) ); col 37 = zeros,
// r=18 hi half = 0 (row-37 padding).
__device__ unsigned g_Mb[38 * 19];
__device__ float g_num[BATCH];
__device__ int   g_msum[BATCH];
__device__ float g_chunk[BATCH * NCH];
__device__ int   g_done;

// ---- helpers ----------------------------------------------------------------
// pack (e, o) -> bf16x2 {lo=e, hi=o}
__device__ __forceinline__ unsigned packbf(float e, float o) {
    unsigned r;
    asm("cvt.rn.bf16x2.f32 %0, %1, %2;" : "=r"(r) : "f"(o), "f"(e));
    return r;
}
__device__ __forceinline__ void hfma2(unsigned& acc, unsigned a, unsigned b) {
    asm("fma.rn.bf16x2 %0, %1, %2, %0;" : "+r"(acc) : "r"(a), "r"(b));
}
__device__ __forceinline__ unsigned hadd2b(unsigned a, unsigned b) {
    unsigned c;
    asm("add.rn.bf16x2 %0, %1, %2;" : "=r"(c) : "r"(a), "r"(b));
    return c;
}
__device__ __forceinline__ unsigned hmul2b(unsigned a, unsigned b) {
    unsigned c;
    asm("mul.rn.bf16x2 %0, %1, %2;" : "=r"(c) : "r"(a), "r"(b));
    return c;
}
__device__ __forceinline__ unsigned swap16(unsigned a) {
    unsigned c;
    asm("prmt.b32 %0, %1, %1, 0x1032;" : "=r"(c) : "r"(a));
    return c;
}
// (a.lo16, b.hi16)
__device__ __forceinline__ unsigned lohi(unsigned a, unsigned b) {
    unsigned c;
    asm("prmt.b32 %0, %1, %2, 0x7610;" : "=r"(c) : "r"(a), "r"(b));
    return c;
}
__device__ __forceinline__ float bflo(unsigned v) {
    return __uint_as_float(v << 16);
}
__device__ __forceinline__ float bfhi(unsigned v) {
    return __uint_as_float(v & 0xffff0000u);
}

// ---------------------------------------------------------------------------
// Kernel 1: numerator, one block per batch; block 0 also preps M (bf16x2)
// ---------------------------------------------------------------------------
__global__ void num_kernel(const float* __restrict__ em,
                           const float* __restrict__ trans,
                           const float* __restrict__ startt,
                           const float* __restrict__ endt,
                           const int*   __restrict__ labels,
                           const int*   __restrict__ mask) {
    int b = blockIdx.x, tid = threadIdx.x;
    if (b == 0) {
        for (int x = tid; x < 38 * 19; x += 256) {
            int j = x / 19, r = x % 19;
            float lo = 0.0f, hi = 0.0f;
            if (j < LSTATE) {
                lo = expf(trans[(2 * r) * LSTATE + j]);
                if (2 * r + 1 < LSTATE)
                    hi = expf(trans[(2 * r + 1) * LSTATE + j]);
            }
            g_Mb[x] = packbf(lo, hi);
        }
        if (tid == 0) g_done = 0;
    }

    __shared__ float sacc[8];
    __shared__ int   snt[8];
    const int*   lb = labels + (size_t)b * TLEN;
    const int*   mk = mask   + (size_t)b * TLEN;
    const float* eb = em     + (size_t)b * TLEN * LSTATE;

    float acc = 0.0f; int msum = 0;
    for (int t = tid; t < TLEN; t += 256) {
        int lt = lb[t]; int m = mk[t]; msum += m;
        if (t == 0) acc += startt[lt] + eb[lt];
        else if (m) acc += trans[lb[t - 1] * LSTATE + lt]
                         + eb[(size_t)t * LSTATE + lt];
    }
    int lane = tid & 31, wid = tid >> 5;
    #pragma unroll
    for (int o = 16; o; o >>= 1) {
        acc  += __shfl_xor_sync(FULLMASK, acc,  o);
        msum += __shfl_xor_sync(FULLMASK, msum, o);
    }
    if (lane == 0) { sacc[wid] = acc; snt[wid] = msum; }
    __syncthreads();
    if (tid == 0) {
        float a = 0.0f; int n = 0;
        #pragma unroll
        for (int k = 0; k < 8; k++) { a += sacc[k]; n += snt[k]; }
        g_num[b]  = a + endt[lb[n - 1]];
        g_msum[b] = n;
    }
}

// ---------------------------------------------------------------------------
// Kernel 2: chunked forward, all-bf16 pipeline. One warp per chunk pair.
// 4 warps/block; grid 1024 (= BATCH*NCH/8); 5 blocks/SM target.
// ---------------------------------------------------------------------------
__global__ void __launch_bounds__(128, 5)
fwd_kernel(const float* __restrict__ em,
           const float* __restrict__ startt,
           const float* __restrict__ endt,
           const int*   __restrict__ mask,
           float* __restrict__ out) {
    __shared__ float fr[4];
    __shared__ int   fn[4];
    __shared__ int   isLast;

    int tid  = threadIdx.x;
    int lane = tid & 31;
    int w    = tid >> 5;
    int wt   = blockIdx.x * 4 + w;      // 0..4095
    int b    = wt >> 3;                 // 0..511
    int cA   = (wt & 7) * 2;            // 0,2,...,14
    int cB   = cA + 1;

    const float* eb = em   + (size_t)b * TLEN * LSTATE;
    const int*   mk = mask + (size_t)b * TLEN;

    bool act   = (lane < 19);
    int  kc    = act ? lane : 18;
    int  col0  = 2 * kc;
    bool hasHi = (col0 + 1 < LSTATE);        // false only for lane 18
    int  col1  = hasHi ? (col0 + 1) : col0;

    // M columns (bf16x2 i-pairs): even col and odd col (odd col 37 -> zeros)
    unsigned MEb[19], MOb[19];
    {
        const unsigned* ce = g_Mb + col0 * 19;
        int oc = hasHi ? (col0 + 1) : 37;
        const unsigned* co = g_Mb + oc * 19;
        #pragma unroll
        for (int k = 0; k < 19; k++) { MEb[k] = ce[k]; MOb[k] = co[k]; }
    }

    // chain states: one bf16x2 each (lo = even col, hi = odd col)
    unsigned qA, qB;
    if (cA == 0) {
        qA = packbf(expf(startt[col0] + eb[col0]),
                    hasHi ? expf(startt[col1] + eb[col1]) : 0.0f);
    } else {
        qA = packbf(1.0f, hasHi ? 1.0f : 0.0f);
    }
    qB = packbf(1.0f, hasHi ? 1.0f : 0.0f);

    int t0a = cA * CSTEP - (WARM - 1);
    const float* ebc0 = eb + col0;
    const float* ebc1 = eb + col1;

    // PF-slot prefetch: exp(emission pair) as bf16x2
    unsigned eeA[PF], eeB[PF];
    #pragma unroll
    for (int d = 0; d < PF; d++) {
        int ta  = t0a + d;
        int tca = ta < 0 ? 0 : (ta >= TLEN ? TLEN - 1 : ta);
        eeA[d] = packbf(__expf(ebc0[(size_t)tca * LSTATE]),
                        hasHi ? __expf(ebc1[(size_t)tca * LSTATE]) : 0.0f);
        int tb  = ta + CSTEP;
        int tcb = tb >= TLEN ? TLEN - 1 : tb;
        eeB[d] = packbf(__expf(ebc0[(size_t)tcb * LSTATE]),
                        hasHi ? __expf(ebc1[(size_t)tcb * LSTATE]) : 0.0f);
    }

    unsigned mwA = 0, mwB = 0;    // 32-step mask words (ballot-loaded)
    int   kta = 0, ktb = 0;
    float subA = 0.0f, subB = 0.0f;

    for (int gg = 0; gg < NGROUPS / 2; gg++) {   // 18 iterations of 8 steps
        int g0 = gg * 2;
        if (g0 == WARMG) {   // warm boundary: reference log-mass (no kt reset)
            float va = act ? (bflo(qA) + bfhi(qA)) : 0.0f;
            float vb = act ? (bflo(qB) + bfhi(qB)) : 0.0f;
            #pragma unroll
            for (int o = 16; o; o >>= 1) {
                va += __shfl_xor_sync(FULLMASK, va, o);
                vb += __shfl_xor_sync(FULLMASK, vb, o);
            }
            subA = (cA == 0) ? 0.0f
                 : (float)((double)kta * 0.6931471805599453) + logf(va);
            subB = (float)((double)ktb * 0.6931471805599453) + logf(vb);
        }
        if ((g0 & 7) == 0) {   // reload mask words every 32 steps
            int ta = t0a + g0 * PF + lane;
            int ia = ta < 0 ? 0 : (ta >= TLEN ? TLEN - 1 : ta);
            mwA = __ballot_sync(FULLMASK,
                                (ta >= 1 && ta < TLEN) && (mk[ia] != 0));
            int tb2 = ta + CSTEP;
            int ib = tb2 >= TLEN ? TLEN - 1 : tb2;
            mwB = __ballot_sync(FULLMASK,
                                (tb2 >= 1 && tb2 < TLEN) && (mk[ib] != 0));
        }
        int shb = (g0 & 7) * PF;

        #pragma unroll
        for (int h = 0; h < 2; h++) {
            #pragma unroll
            for (int u = 0; u < PF; u++) {
                int g = g0 + h;
                unsigned eA = eeA[u], eB2 = eeB[u];
                int mcA = (mwA >> (shb + h * PF + u)) & 1;
                int mcB = (mwB >> (shb + h * PF + u)) & 1;

                {   // refill slot u for step t + PF (off critical path)
                    int ta  = t0a + g * PF + u + PF;
                    int tca = ta < 0 ? 0 : (ta >= TLEN ? TLEN - 1 : ta);
                    eeA[u] = packbf(__expf(ebc0[(size_t)tca * LSTATE]),
                                    hasHi ? __expf(ebc1[(size_t)tca * LSTATE])
                                          : 0.0f);
                    int tb  = ta + CSTEP;
                    int tcb = tb >= TLEN ? TLEN - 1 : tb;
                    eeB[u] = packbf(__expf(ebc0[(size_t)tcb * LSTATE]),
                                    hasHi ? __expf(ebc1[(size_t)tcb * LSTATE])
                                          : 0.0f);
                }

                // ---- bf16x2 broadcasts + native bf16x2 FMA, both chains ----
                unsigned xE0 = 0, xE1 = 0, xO0 = 0, xO1 = 0;   // chain A
                unsigned yE0 = 0, yE1 = 0, yO0 = 0, yO1 = 0;   // chain B
                unsigned q0a = 0, q0b = 0;
                #pragma unroll
                for (int r = 0; r < 19; r++) {
                    unsigned va = __shfl_sync(FULLMASK, qA, r);
                    unsigned vb = __shfl_sync(FULLMASK, qB, r);
                    if (r == 0) { q0a = va; q0b = vb; }
                    if (r & 1) {
                        hfma2(xE1, va, MEb[r]); hfma2(xO1, va, MOb[r]);
                        hfma2(yE1, vb, MEb[r]); hfma2(yO1, vb, MOb[r]);
                    } else {
                        hfma2(xE0, va, MEb[r]); hfma2(xO0, va, MOb[r]);
                        hfma2(yE0, vb, MEb[r]); hfma2(yO0, vb, MOb[r]);
                    }
                }
                // column sums in bf16: (sE,sE) and (sO,sO) -> (sE,sO)
                unsigned zE = hadd2b(xE0, xE1);
                unsigned zO = hadd2b(xO0, xO1);
                unsigned sA = lohi(hadd2b(zE, swap16(zE)),
                                   hadd2b(zO, swap16(zO)));
                unsigned zE2 = hadd2b(yE0, yE1);
                unsigned zO2 = hadd2b(yO0, yO1);
                unsigned sB = lohi(hadd2b(zE2, swap16(zE2)),
                                   hadd2b(zO2, swap16(zO2)));

                unsigned nA = hmul2b(sA, eA);
                unsigned nB = hmul2b(sB, eB2);
                qA = mcA ? nA : qA;
                qB = mcB ? nB : qB;

                if (h == 1 && u == PF - 1) {   // renorm every 8 steps
                    unsigned ea_ = (q0a >> 7) & 0xffu;   // bf16-lo exp of q0
                    unsigned sa16 = (254u - ea_) << 7;
                    qA = hmul2b(qA, sa16 * 0x10001u);
                    kta += (int)ea_ - 127;
                    unsigned eb_ = (q0b >> 7) & 0xffu;
                    unsigned sb16 = (254u - eb_) << 7;
                    qB = hmul2b(qB, sb16 * 0x10001u);
                    ktb += (int)eb_ - 127;
                }
            }
        }
    }

    // chunk contributions (ktot*ln2 + log S_end - sub); end weights for c==15
    {
        float va = act ? (bflo(qA) + bfhi(qA)) : 0.0f;
        float vb;
        if (cB == NCH - 1)
            vb = act ? (bflo(qB) * expf(endt[col0])
                        + (hasHi ? bfhi(qB) * expf(endt[col1]) : 0.0f)) : 0.0f;
        else
            vb = act ? (bflo(qB) + bfhi(qB)) : 0.0f;
        #pragma unroll
        for (int o = 16; o; o >>= 1) {
            va += __shfl_xor_sync(FULLMASK, va, o);
            vb += __shfl_xor_sync(FULLMASK, vb, o);
        }
        if (lane == 0) {
            g_chunk[b * NCH + cA] =
                (float)((double)kta * 0.6931471805599453) + logf(va) - subA;
            g_chunk[b * NCH + cB] =
                (float)((double)ktb * 0.6931471805599453) + logf(vb) - subB;
        }
    }

    // ---- fused finish: last block reduces everything ----
    __threadfence();
    __syncthreads();
    if (tid == 0)
        isLast = (atomicAdd(&g_done, 1) == (int)gridDim.x - 1);
    __syncthreads();

    if (isLast) {
        __threadfence();
        float acc = 0.0f; int nt = 0;
        for (int i = tid; i < BATCH; i += 128) {
            float d = 0.0f;
            #pragma unroll
            for (int cc = 0; cc < NCH; cc++) d += g_chunk[i * NCH + cc];
            acc += g_num[i] - d;
            nt  += g_msum[i];
        }
        #pragma unroll
        for (int o = 16; o; o >>= 1) {
            acc += __shfl_xor_sync(FULLMASK, acc, o);
            nt  += __shfl_xor_sync(FULLMASK, nt,  o);
        }
        if (lane == 0) { fr[w] = acc; fn[w] = nt; }
        __syncthreads();
        if (tid == 0) {
            float tot = fr[0] + fr[1] + fr[2] + fr[3];
            int   n   = fn[0] + fn[1] + fn[2] + fn[3];
            if (n < 1) n = 1;
            out[0] = -tot / (float)n;
        }
    }
}

// ---------------------------------------------------------------------------
// Launch
// ---------------------------------------------------------------------------
extern "C" void kernel_launch(void* const* d_in, const int* in_sizes, int n_in,
                              void* d_out, int out_size) {
    const float* em     = (const float*)d_in[0];   // emissions [512,2048,37]
    const float* trans  = (const float*)d_in[1];   // transitions [37,37]
    const float* startt = (const float*)d_in[2];   // start_transitions [37]
    const float* endt   = (const float*)d_in[3];   // end_transitions [37]
    const int*   labels = (const int*)d_in[4];     // labels [512,2048]
    const int*   mask   = (const int*)d_in[5];     // attention_mask [512,2048]

    num_kernel<<<BATCH, 256>>>(em, trans, startt, endt, labels, mask);
    // 8 chunks per block (4 warps x 2 chains) -> BATCH*NCH/8 = 1024 blocks
    fwd_kernel<<<BATCH * NCH / 8, 128>>>(em, startt, endt, mask, (float*)d_out);
}